// round 15
// baseline (speedup 1.0000x reference)
#include <cuda_runtime.h>
#include <cuda_fp16.h>
#include <cstdint>

#define N_PIX  4096
#define C_IN   256
#define B_SZ   4
#define TN     64
#define NTILES (N_PIX / TN)     // 64
#define M_TILE 64

// ---- flash smem byte offsets (M_TILE=64, TN=64, occ-2, all double-buffered) ----
#define SQ   0                           // [64 m][32 d] fp16, stride 80 (5120)
#define SKB(st) (5120 + (st) * 5120)     // [64 n][32 d] fp16, stride 80, 2 stages
#define SVB(st) (15360 + (st) * 33792)   // [64 n][256 c] fp16, stride 528, 2 stages
#define SPB(st) (82944 + (st) * 9216)    // [64 m][64 k] fp16, stride 144, 2 stages
#define SLP  101376                      // 2 x 64 float partial row sums
#define SMEM_TOTAL 101888

#define QK_STR 80
#define P_STR  144
#define V_STR  528

// ---- proj2 smem layout ----
#define PW_STR 528
#define PX_STR 528
#define PSW    0
#define PSX(st) (16896 + (st) * 16896)
#define PSMEM  50688

// ---------------- device scratch ----------------
__device__ __align__(16) __half g_Qs[B_SZ * N_PIX * 32];            // [b][m][32 d], scale*log2e folded
__device__ __align__(16) __half g_Ks[B_SZ * N_PIX * 32];            // [b][n][32 d]
__device__ __align__(16) __half g_V[(size_t)B_SZ * N_PIX * C_IN];   // [b][n][c]
__device__ __align__(16) float g_Wf[320 * C_IN];
__device__ float g_Bf[320];

// ---------------- helpers ----------------
__device__ __forceinline__ uint32_t s2u(const void* p) {
    uint32_t a;
    asm("{ .reg .u64 t; cvta.to.shared.u64 t, %1; cvt.u32.u64 %0, t; }" : "=r"(a) : "l"(p));
    return a;
}
__device__ __forceinline__ void cp16(uint32_t dst, const void* src) {
    asm volatile("cp.async.cg.shared.global [%0], [%1], 16;\n" :: "r"(dst), "l"(src));
}
#define CP_COMMIT() asm volatile("cp.async.commit_group;\n" ::: "memory")
#define CP_WAITN(n) asm volatile("cp.async.wait_group %0;\n" :: "n"(n) : "memory")

__device__ __forceinline__ void ldsm4(uint32_t& r0, uint32_t& r1, uint32_t& r2, uint32_t& r3, uint32_t a) {
    asm volatile("ldmatrix.sync.aligned.m8n8.x4.shared.b16 {%0,%1,%2,%3}, [%4];"
                 : "=r"(r0), "=r"(r1), "=r"(r2), "=r"(r3) : "r"(a));
}
__device__ __forceinline__ void ldsm4t(uint32_t& r0, uint32_t& r1, uint32_t& r2, uint32_t& r3, uint32_t a) {
    asm volatile("ldmatrix.sync.aligned.m8n8.x4.trans.shared.b16 {%0,%1,%2,%3}, [%4];"
                 : "=r"(r0), "=r"(r1), "=r"(r2), "=r"(r3) : "r"(a));
}
__device__ __forceinline__ void stsm4(uint32_t a, uint32_t r0, uint32_t r1, uint32_t r2, uint32_t r3) {
    asm volatile("stmatrix.sync.aligned.m8n8.x4.shared.b16 [%0], {%1,%2,%3,%4};"
                 :: "r"(a), "r"(r0), "r"(r1), "r"(r2), "r"(r3) : "memory");
}
__device__ __forceinline__ void mma_f16(float* c, uint32_t a0, uint32_t a1, uint32_t a2, uint32_t a3,
                                        uint32_t b0, uint32_t b1) {
    asm volatile(
        "mma.sync.aligned.m16n8k16.row.col.f32.f16.f16.f32 "
        "{%0,%1,%2,%3}, {%4,%5,%6,%7}, {%8,%9}, {%0,%1,%2,%3};"
        : "+f"(c[0]), "+f"(c[1]), "+f"(c[2]), "+f"(c[3])
        : "r"(a0), "r"(a1), "r"(a2), "r"(a3), "r"(b0), "r"(b1));
}
__device__ __forceinline__ float ex2f(float x) {
    float e; asm("ex2.approx.ftz.f32 %0, %1;" : "=f"(e) : "f"(x)); return e;
}

// ---------------- fold BN into 1x1-conv weights ----------------
__global__ void fold_kernel(
    const float* __restrict__ qw, const float* __restrict__ qb,
    const float* __restrict__ qg, const float* __restrict__ qbe,
    const float* __restrict__ qm, const float* __restrict__ qv,
    const float* __restrict__ kw, const float* __restrict__ kb,
    const float* __restrict__ kg, const float* __restrict__ kbe,
    const float* __restrict__ km, const float* __restrict__ kv,
    const float* __restrict__ vw, const float* __restrict__ vb,
    const float* __restrict__ vg, const float* __restrict__ vbe,
    const float* __restrict__ vm, const float* __restrict__ vv)
{
    int r = blockIdx.x;
    const float *w, *bb, *g, *be, *mn, *vr; int j;
    if (r < 32)      { w = qw; bb = qb; g = qg; be = qbe; mn = qm; vr = qv; j = r; }
    else if (r < 64) { w = kw; bb = kb; g = kg; be = kbe; mn = km; vr = kv; j = r - 32; }
    else             { w = vw; bb = vb; g = vg; be = vbe; mn = vm; vr = vv; j = r - 64; }
    float inv = g[j] * rsqrtf(vr[j] + 1e-5f);
    int c = threadIdx.x;
    g_Wf[r * C_IN + c] = w[j * C_IN + c] * inv;
    if (c == 0) g_Bf[r] = bb[j] * inv + be[j] - mn[j] * inv;
}

// ---------------- projection via tensor cores (unchanged R14) ----------------
__global__ __launch_bounds__(256) void proj2_kernel(
    const float* __restrict__ x1, const float* __restrict__ x2)
{
    __shared__ __align__(16) char sm[PSMEM];
    const uint32_t sb = s2u(sm);
    const int seg = blockIdx.y, b = blockIdx.z;
    const int tid = threadIdx.x;
    const int warp = tid >> 5, lane = tid & 31;
    const int nw = warp * 32;
    const int px0 = blockIdx.x * 256;
    const int r0 = seg * 32;
    const float qs = (seg == 0) ? (0.17677669529663689f * 1.4426950408889634f) : 1.0f;

    for (int i = tid; i < 2048; i += 256) {
        int m = i >> 6, k4 = i & 63;
        float4 w = *(const float4*)&g_Wf[(r0 + m) * C_IN + k4 * 4];
        __half2 h0 = __floats2half2_rn(w.x * qs, w.y * qs);
        __half2 h1 = __floats2half2_rn(w.z * qs, w.w * qs);
        *(uint2*)(sm + PSW + m * PW_STR + k4 * 8) =
            make_uint2(*reinterpret_cast<uint32_t*>(&h0), *reinterpret_cast<uint32_t*>(&h1));
    }

    const float* xb = ((seg == 0) ? x1 : x2) + (size_t)b * C_IN * N_PIX + px0;

    auto cvt_store = [&](const float4* f, int st) {
#pragma unroll
        for (int u = 0; u < 8; ++u) {
            int i = tid + u * 256;
            int c = i >> 6, n4 = i & 63;
            __half2 h0 = __floats2half2_rn(f[u].x, f[u].y);
            __half2 h1 = __floats2half2_rn(f[u].z, f[u].w);
            *(uint2*)(sm + PSX(st) + c * PX_STR + n4 * 8) =
                make_uint2(*reinterpret_cast<uint32_t*>(&h0), *reinterpret_cast<uint32_t*>(&h1));
        }
    };
    auto load_x = [&](int ch, float4* f) {
        const float* xs = xb + (size_t)(ch * 32) * N_PIX;
#pragma unroll
        for (int u = 0; u < 8; ++u) {
            int i = tid + u * 256;
            int c = i >> 6, n4 = i & 63;
            f[u] = *(const float4*)&xs[(size_t)c * N_PIX + n4 * 4];
        }
    };

    float O[2][4][4];
#pragma unroll
    for (int mt = 0; mt < 2; ++mt)
#pragma unroll
        for (int j = 0; j < 4; ++j)
#pragma unroll
            for (int k = 0; k < 4; ++k) O[mt][j][k] = 0.f;

    {
        float4 f[8];
        load_x(0, f);
        cvt_store(f, 0);
    }
    __syncthreads();

#pragma unroll 1
    for (int ch = 0; ch < 8; ++ch) {
        const int st = ch & 1;
        float4 f[8];
        if (ch < 7) load_x(ch + 1, f);

#pragma unroll
        for (int kt = 0; kt < 2; ++kt) {
            uint32_t a0[4], a1[4];
            ldsm4(a0[0], a0[1], a0[2], a0[3],
                  sb + PSW + ((lane & 15)) * PW_STR + ch * 64 + kt * 32 + (lane >> 4) * 16);
            ldsm4(a1[0], a1[1], a1[2], a1[3],
                  sb + PSW + (16 + (lane & 15)) * PW_STR + ch * 64 + kt * 32 + (lane >> 4) * 16);
            uint32_t xrow = kt * 16 + ((lane >> 3) & 1) * 8 + (lane & 7);
#pragma unroll
            for (int nb = 0; nb < 2; ++nb) {
                uint32_t colb = nw * 2 + nb * 32 + ((lane >> 4) & 1) * 16;
                uint32_t b0, b1, b2, b3;
                ldsm4t(b0, b1, b2, b3, sb + PSX(st) + xrow * PX_STR + colb);
                int j = nb * 2;
                mma_f16(O[0][j],     a0[0], a0[1], a0[2], a0[3], b0, b1);
                mma_f16(O[0][j + 1], a0[0], a0[1], a0[2], a0[3], b2, b3);
                mma_f16(O[1][j],     a1[0], a1[1], a1[2], a1[3], b0, b1);
                mma_f16(O[1][j + 1], a1[0], a1[1], a1[2], a1[3], b2, b3);
            }
        }

        if (ch < 7) cvt_store(f, st ^ 1);
        __syncthreads();
    }

    {
        int g = lane >> 3;
#pragma unroll
        for (int mt = 0; mt < 2; ++mt) {
            float bias0 = g_Bf[r0 + mt * 16 + (lane >> 2)] * qs;
            float bias1 = g_Bf[r0 + mt * 16 + (lane >> 2) + 8] * qs;
            uint32_t p01[4], p23[4];
#pragma unroll
            for (int j = 0; j < 4; ++j) {
                __half2 h01 = __floats2half2_rn(O[mt][j][0] + bias0, O[mt][j][1] + bias0);
                __half2 h23 = __floats2half2_rn(O[mt][j][2] + bias1, O[mt][j][3] + bias1);
                p01[j] = *reinterpret_cast<uint32_t*>(&h01);
                p23[j] = *reinterpret_cast<uint32_t*>(&h23);
            }
            uint32_t row = mt * 16 + (g & 1) * 8 + (lane & 7);
            uint32_t colb = nw * 2 + (g >> 1) * 16;
            uint32_t a0 = sb + PSX(0) + row * PX_STR + colb;
            stsm4(a0,      p01[0], p23[0], p01[1], p23[1]);
            stsm4(a0 + 32, p01[2], p23[2], p01[3], p23[3]);
        }
    }
    __syncthreads();

    {
        uint32_t h[16];
#pragma unroll
        for (int j = 0; j < 16; ++j) {
            uint16_t lo, hi;
            asm volatile("ld.shared.u16 %0, [%1];" : "=h"(lo)
                         : "r"(sb + PSX(0) + (2 * j) * PX_STR + tid * 2));
            asm volatile("ld.shared.u16 %0, [%1];" : "=h"(hi)
                         : "r"(sb + PSX(0) + (2 * j + 1) * PX_STR + tid * 2));
            h[j] = (uint32_t)lo | ((uint32_t)hi << 16);
        }
        char* dst;
        if (seg < 2)
            dst = (char*)((seg == 0) ? g_Qs : g_Ks) + ((size_t)(b * N_PIX + px0 + tid)) * 64;
        else
            dst = (char*)g_V + (((size_t)(b * N_PIX + px0 + tid)) * C_IN + (seg - 2) * 32) * 2;
#pragma unroll
        for (int q = 0; q < 4; ++q)
            *(uint4*)(dst + q * 16) = make_uint4(h[4 * q], h[4 * q + 1], h[4 * q + 2], h[4 * q + 3]);
    }
}

// ---------------- flash attention: pipelined softmax(t) under PV(t-1) ----------------
// grid: (N_PIX/64, B), 256 threads = 8 warps, occ 2.
// S phase:  warp w -> m-slice (w&3)*16, n-half (w>>2)*32
// PV phase: warp w -> m-slice (w&1)*32 (two m16 tiles), c-quarter (w>>1)*64
__global__ __launch_bounds__(256, 2) void flash_mma(float* __restrict__ out)
{
    extern __shared__ __align__(16) char sm[];
    const uint32_t sb = s2u(sm);
    const int tid  = threadIdx.x;
    const int warp = tid >> 5;
    const int lane = tid & 31;
    const int ms   = (warp & 3) * 16;
    const int half = warp >> 2;
    const int mw   = (warp & 1) * 32;
    const int cq   = (warp >> 1) * 64;
    const int b    = blockIdx.y;
    const int m_base = blockIdx.x * M_TILE;

    const char* gkb = (const char*)g_Ks + ((size_t)b * N_PIX) * 64;
    const char* gvb = (const char*)g_V + ((size_t)b * N_PIX) * C_IN * 2;

    // ---- Q -> smem ----
    {
        const char* gq = (const char*)g_Qs + ((size_t)(b * N_PIX + m_base)) * 64;
        int m = tid >> 2, q = tid & 3;
        uint4 v = *(const uint4*)(gq + (size_t)m * 64 + q * 16);
        *(uint4*)(sm + SQ + m * QK_STR + q * 16) = v;
    }

    auto load_k = [&](int t, int st) {
        const char* gk = gkb + (size_t)t * TN * 64;
        int n = tid >> 2, q = tid & 3;
        cp16(sb + SKB(st) + n * QK_STR + q * 16, gk + (size_t)n * 64 + q * 16);
    };
    auto load_v = [&](int t, int st) {
        const char* gv = gvb + (size_t)t * TN * C_IN * 2;
        for (int i = tid; i < 2048; i += 256) {
            int n = i >> 5, q = i & 31;
            cp16(sb + SVB(st) + n * V_STR + q * 16, gv + (size_t)n * 512 + q * 16);
        }
    };

    // prologue loads: K(0), V(0)
    load_k(0, 0);
    CP_COMMIT();
    load_v(0, 0);
    CP_COMMIT();
    __syncthreads();   // Q smem ready

    // hoist Q fragments (loop-invariant)
    uint32_t qf[2][4];
#pragma unroll
    for (int kt = 0; kt < 2; ++kt)
        ldsm4(qf[kt][0], qf[kt][1], qf[kt][2], qf[kt][3],
              sb + SQ + (ms + (lane & 15)) * QK_STR + kt * 32 + (lane >> 4) * 16);

    float O[2][8][4];
#pragma unroll
    for (int mt = 0; mt < 2; ++mt)
#pragma unroll
        for (int j = 0; j < 8; ++j)
#pragma unroll
            for (int k = 0; k < 4; ++k) O[mt][j][k] = 0.f;
    float rs0 = 0.f, rs1 = 0.f;

    // PV over tile tt (reads P(tt), V(tt) from stage tt&1)
    auto pv_step = [&](int tt) {
        const int stp = tt & 1;
#pragma unroll
        for (int kt = 0; kt < 4; ++kt) {
            uint32_t p0a, p0b, p0c, p0d, p1a, p1b, p1c, p1d;
            ldsm4(p0a, p0b, p0c, p0d,
                  sb + SPB(stp) + (mw + (lane & 15)) * P_STR + kt * 32 + (lane >> 4) * 16);
            ldsm4(p1a, p1b, p1c, p1d,
                  sb + SPB(stp) + (mw + 16 + (lane & 15)) * P_STR + kt * 32 + (lane >> 4) * 16);
            uint32_t vrow = kt * 16 + ((lane >> 3) & 1) * 8 + (lane & 7);
#pragma unroll
            for (int vb = 0; vb < 4; ++vb) {
                uint32_t colb = cq * 2 + vb * 32 + ((lane >> 4) & 1) * 16;
                uint32_t b0, b1, b2, b3;
                ldsm4t(b0, b1, b2, b3, sb + SVB(stp) + vrow * V_STR + colb);
                int j = vb * 2;
                mma_f16(O[0][j],     p0a, p0b, p0c, p0d, b0, b1);
                mma_f16(O[0][j + 1], p0a, p0b, p0c, p0d, b2, b3);
                mma_f16(O[1][j],     p1a, p1b, p1c, p1d, b0, b1);
                mma_f16(O[1][j + 1], p1a, p1b, p1c, p1d, b2, b3);
            }
        }
    };

#pragma unroll 1
    for (int t = 0; t < NTILES; ++t) {
        const int st = t & 1;
        if (t + 1 < NTILES) {
            load_k(t + 1, st ^ 1);
            CP_COMMIT();
            CP_WAITN(1);   // K(t), V(t) done; K(t+1) in flight
        } else {
            CP_WAITN(0);
        }
        __syncthreads();

        // ---- S(t) = Q K^T, warp tile m16 x n32 ----
        float acc[4][4];
#pragma unroll
        for (int j = 0; j < 4; ++j)
#pragma unroll
            for (int k = 0; k < 4; ++k) acc[j][k] = 0.f;

#pragma unroll
        for (int kt = 0; kt < 2; ++kt) {
#pragma unroll
            for (int nb = 0; nb < 2; ++nb) {
                int nbase = half * 32 + nb * 16;
                uint32_t row = nbase + ((lane >> 4) << 3) + (lane & 7);
                uint32_t col = kt * 32 + ((lane >> 3) & 1) * 16;
                uint32_t b0, b1, b2, b3;
                ldsm4(b0, b1, b2, b3, sb + SKB(st) + row * QK_STR + col);
                mma_f16(acc[2 * nb],     qf[kt][0], qf[kt][1], qf[kt][2], qf[kt][3], b0, b1);
                mma_f16(acc[2 * nb + 1], qf[kt][0], qf[kt][1], qf[kt][2], qf[kt][3], b2, b3);
            }
        }

        // ---- PV(t-1): tensor work that hides softmax(t) latency ----
        if (t > 0) pv_step(t - 1);

        // ---- softmax(t): P = exp2(S) unnormalized; row sums; pack fp16 ----
        uint32_t p01h[4], p23h[4];
#pragma unroll
        for (int j = 0; j < 4; ++j) {
            float p0 = ex2f(acc[j][0]), p1 = ex2f(acc[j][1]);
            float p2 = ex2f(acc[j][2]), p3 = ex2f(acc[j][3]);
            rs0 += p0 + p1;
            rs1 += p2 + p3;
            __half2 h01 = __floats2half2_rn(p0, p1);
            __half2 h23 = __floats2half2_rn(p2, p3);
            p01h[j] = *reinterpret_cast<uint32_t*>(&h01);
            p23h[j] = *reinterpret_cast<uint32_t*>(&h23);
        }

        // ---- stsm P(t) into stage st ----
        {
            int g = lane >> 3;
            uint32_t row = ms + (g & 1) * 8 + (lane & 7);
            uint32_t colb = half * 64 + (g >> 1) * 16;
            uint32_t a0 = sb + SPB(st) + row * P_STR + colb;
            stsm4(a0,      p01h[0], p23h[0], p01h[1], p23h[1]);
            stsm4(a0 + 32, p01h[2], p23h[2], p01h[3], p23h[3]);
        }
        __syncthreads();

        // ---- issue V(t+1) (overlaps next iteration's S) ----
        if (t + 1 < NTILES) {
            load_v(t + 1, st ^ 1);
            CP_COMMIT();
        }
    }

    // final PV
    pv_step(NTILES - 1);

    // ---- epilogue: combine row sums, normalize, store ----
    rs0 += __shfl_xor_sync(0xffffffffu, rs0, 1);
    rs0 += __shfl_xor_sync(0xffffffffu, rs0, 2);
    rs1 += __shfl_xor_sync(0xffffffffu, rs1, 1);
    rs1 += __shfl_xor_sync(0xffffffffu, rs1, 2);
    float* sLp = (float*)(sm + SLP);
    if ((lane & 3) == 0) {
        sLp[half * 64 + ms + (lane >> 2)]     = rs0;
        sLp[half * 64 + ms + (lane >> 2) + 8] = rs1;
    }
    __syncthreads();

    float* ob = out + (size_t)b * C_IN * N_PIX + m_base;
#pragma unroll
    for (int mt = 0; mt < 2; ++mt) {
        int r0 = mw + mt * 16 + (lane >> 2);
        float inv0 = 1.0f / (sLp[r0] + sLp[64 + r0]);
        float inv1 = 1.0f / (sLp[r0 + 8] + sLp[64 + r0 + 8]);
#pragma unroll
        for (int j = 0; j < 8; ++j) {
            int c = cq + j * 8 + 2 * (lane & 3);
            ob[(size_t)c * N_PIX + r0]           = O[mt][j][0] * inv0;
            ob[(size_t)(c + 1) * N_PIX + r0]     = O[mt][j][1] * inv0;
            ob[(size_t)c * N_PIX + r0 + 8]       = O[mt][j][2] * inv1;
            ob[(size_t)(c + 1) * N_PIX + r0 + 8] = O[mt][j][3] * inv1;
        }
    }
}

// ---------------- launch ----------------
extern "C" void kernel_launch(void* const* d_in, const int* in_sizes, int n_in,
                              void* d_out, int out_size)
{
    const float* x1 = (const float*)d_in[0];
    const float* x2 = (const float*)d_in[1];

    fold_kernel<<<320, 256>>>(
        (const float*)d_in[2],  (const float*)d_in[3],  (const float*)d_in[4],
        (const float*)d_in[5],  (const float*)d_in[6],  (const float*)d_in[7],
        (const float*)d_in[8],  (const float*)d_in[9],  (const float*)d_in[10],
        (const float*)d_in[11], (const float*)d_in[12], (const float*)d_in[13],
        (const float*)d_in[14], (const float*)d_in[15], (const float*)d_in[16],
        (const float*)d_in[17], (const float*)d_in[18], (const float*)d_in[19]);

    proj2_kernel<<<dim3(N_PIX / 256, 10, B_SZ), 256>>>(x1, x2);

    cudaFuncSetAttribute(flash_mma, cudaFuncAttributeMaxDynamicSharedMemorySize, SMEM_TOTAL);
    flash_mma<<<dim3(N_PIX / M_TILE, B_SZ), 256, SMEM_TOTAL>>>((float*)d_out);
}

// round 16
// speedup vs baseline: 1.1046x; 1.1046x over previous
#include <cuda_runtime.h>
#include <cuda_fp16.h>
#include <cstdint>

#define N_PIX  4096
#define C_IN   256
#define B_SZ   4
#define TN     128
#define NTILES (N_PIX / TN)     // 32
#define M_TILE 64

// ---- flash smem byte offsets (M_TILE=64, occ-2) ----
#define SQ   0                          // [64 m][32 d] fp16, stride 80  (5120)
#define SKB(st) (5120 + (st) * 10240)   // [128 n][32 d] fp16, stride 80 (2 stages)
#define SV   25600                      // [128 n][256 c] fp16, stride 528 (67584)
#define SP   93184                      // [64 m][128 k] fp16, stride 272 (17408)
#define SLP  110592                     // 2 x 64 float partial row sums (512)
#define SMEM_TOTAL 111104

#define QK_STR 80
#define P_STR  272
#define V_STR  528
#define T_STR  68                       // epilogue staging stride (floats)

// ---- proj2 smem layout ----
#define PW_STR 528
#define PX_STR 528
#define PSW    0
#define PSX(st) (16896 + (st) * 16896)
#define PSMEM  50688

// ---------------- device scratch ----------------
__device__ __align__(16) __half g_Qs[B_SZ * N_PIX * 32];            // [b][m][32 d], scale*log2e folded
__device__ __align__(16) __half g_Ks[B_SZ * N_PIX * 32];            // [b][n][32 d]
__device__ __align__(16) __half g_V[(size_t)B_SZ * N_PIX * C_IN];   // [b][n][c]
__device__ __align__(16) float g_Wf[320 * C_IN];
__device__ float g_Bf[320];

// ---------------- helpers ----------------
__device__ __forceinline__ uint32_t s2u(const void* p) {
    uint32_t a;
    asm("{ .reg .u64 t; cvta.to.shared.u64 t, %1; cvt.u32.u64 %0, t; }" : "=r"(a) : "l"(p));
    return a;
}
__device__ __forceinline__ void cp16(uint32_t dst, const void* src) {
    asm volatile("cp.async.cg.shared.global [%0], [%1], 16;\n" :: "r"(dst), "l"(src));
}
#define CP_COMMIT() asm volatile("cp.async.commit_group;\n" ::: "memory")
#define CP_WAITN(n) asm volatile("cp.async.wait_group %0;\n" :: "n"(n) : "memory")

__device__ __forceinline__ void ldsm4(uint32_t& r0, uint32_t& r1, uint32_t& r2, uint32_t& r3, uint32_t a) {
    asm volatile("ldmatrix.sync.aligned.m8n8.x4.shared.b16 {%0,%1,%2,%3}, [%4];"
                 : "=r"(r0), "=r"(r1), "=r"(r2), "=r"(r3) : "r"(a));
}
__device__ __forceinline__ void ldsm4t(uint32_t& r0, uint32_t& r1, uint32_t& r2, uint32_t& r3, uint32_t a) {
    asm volatile("ldmatrix.sync.aligned.m8n8.x4.trans.shared.b16 {%0,%1,%2,%3}, [%4];"
                 : "=r"(r0), "=r"(r1), "=r"(r2), "=r"(r3) : "r"(a));
}
__device__ __forceinline__ void stsm4(uint32_t a, uint32_t r0, uint32_t r1, uint32_t r2, uint32_t r3) {
    asm volatile("stmatrix.sync.aligned.m8n8.x4.shared.b16 [%0], {%1,%2,%3,%4};"
                 :: "r"(a), "r"(r0), "r"(r1), "r"(r2), "r"(r3) : "memory");
}
__device__ __forceinline__ void mma_f16(float* c, uint32_t a0, uint32_t a1, uint32_t a2, uint32_t a3,
                                        uint32_t b0, uint32_t b1) {
    asm volatile(
        "mma.sync.aligned.m16n8k16.row.col.f32.f16.f16.f32 "
        "{%0,%1,%2,%3}, {%4,%5,%6,%7}, {%8,%9}, {%0,%1,%2,%3};"
        : "+f"(c[0]), "+f"(c[1]), "+f"(c[2]), "+f"(c[3])
        : "r"(a0), "r"(a1), "r"(a2), "r"(a3), "r"(b0), "r"(b1));
}
__device__ __forceinline__ float ex2f(float x) {
    float e; asm("ex2.approx.ftz.f32 %0, %1;" : "=f"(e) : "f"(x)); return e;
}

// ---------------- fold BN into 1x1-conv weights ----------------
__global__ void fold_kernel(
    const float* __restrict__ qw, const float* __restrict__ qb,
    const float* __restrict__ qg, const float* __restrict__ qbe,
    const float* __restrict__ qm, const float* __restrict__ qv,
    const float* __restrict__ kw, const float* __restrict__ kb,
    const float* __restrict__ kg, const float* __restrict__ kbe,
    const float* __restrict__ km, const float* __restrict__ kv,
    const float* __restrict__ vw, const float* __restrict__ vb,
    const float* __restrict__ vg, const float* __restrict__ vbe,
    const float* __restrict__ vm, const float* __restrict__ vv)
{
    int r = blockIdx.x;
    const float *w, *bb, *g, *be, *mn, *vr; int j;
    if (r < 32)      { w = qw; bb = qb; g = qg; be = qbe; mn = qm; vr = qv; j = r; }
    else if (r < 64) { w = kw; bb = kb; g = kg; be = kbe; mn = km; vr = kv; j = r - 32; }
    else             { w = vw; bb = vb; g = vg; be = vbe; mn = vm; vr = vv; j = r - 64; }
    float inv = g[j] * rsqrtf(vr[j] + 1e-5f);
    int c = threadIdx.x;
    g_Wf[r * C_IN + c] = w[j * C_IN + c] * inv;
    if (c == 0) g_Bf[r] = bb[j] * inv + be[j] - mn[j] * inv;
}

// ---------------- projection via tensor cores (unchanged R14) ----------------
__global__ __launch_bounds__(256) void proj2_kernel(
    const float* __restrict__ x1, const float* __restrict__ x2)
{
    __shared__ __align__(16) char sm[PSMEM];
    const uint32_t sb = s2u(sm);
    const int seg = blockIdx.y, b = blockIdx.z;
    const int tid = threadIdx.x;
    const int warp = tid >> 5, lane = tid & 31;
    const int nw = warp * 32;
    const int px0 = blockIdx.x * 256;
    const int r0 = seg * 32;
    const float qs = (seg == 0) ? (0.17677669529663689f * 1.4426950408889634f) : 1.0f;

    for (int i = tid; i < 2048; i += 256) {
        int m = i >> 6, k4 = i & 63;
        float4 w = *(const float4*)&g_Wf[(r0 + m) * C_IN + k4 * 4];
        __half2 h0 = __floats2half2_rn(w.x * qs, w.y * qs);
        __half2 h1 = __floats2half2_rn(w.z * qs, w.w * qs);
        *(uint2*)(sm + PSW + m * PW_STR + k4 * 8) =
            make_uint2(*reinterpret_cast<uint32_t*>(&h0), *reinterpret_cast<uint32_t*>(&h1));
    }

    const float* xb = ((seg == 0) ? x1 : x2) + (size_t)b * C_IN * N_PIX + px0;

    auto cvt_store = [&](const float4* f, int st) {
#pragma unroll
        for (int u = 0; u < 8; ++u) {
            int i = tid + u * 256;
            int c = i >> 6, n4 = i & 63;
            __half2 h0 = __floats2half2_rn(f[u].x, f[u].y);
            __half2 h1 = __floats2half2_rn(f[u].z, f[u].w);
            *(uint2*)(sm + PSX(st) + c * PX_STR + n4 * 8) =
                make_uint2(*reinterpret_cast<uint32_t*>(&h0), *reinterpret_cast<uint32_t*>(&h1));
        }
    };
    auto load_x = [&](int ch, float4* f) {
        const float* xs = xb + (size_t)(ch * 32) * N_PIX;
#pragma unroll
        for (int u = 0; u < 8; ++u) {
            int i = tid + u * 256;
            int c = i >> 6, n4 = i & 63;
            f[u] = *(const float4*)&xs[(size_t)c * N_PIX + n4 * 4];
        }
    };

    float O[2][4][4];
#pragma unroll
    for (int mt = 0; mt < 2; ++mt)
#pragma unroll
        for (int j = 0; j < 4; ++j)
#pragma unroll
            for (int k = 0; k < 4; ++k) O[mt][j][k] = 0.f;

    {
        float4 f[8];
        load_x(0, f);
        cvt_store(f, 0);
    }
    __syncthreads();

#pragma unroll 1
    for (int ch = 0; ch < 8; ++ch) {
        const int st = ch & 1;
        float4 f[8];
        if (ch < 7) load_x(ch + 1, f);

#pragma unroll
        for (int kt = 0; kt < 2; ++kt) {
            uint32_t a0[4], a1[4];
            ldsm4(a0[0], a0[1], a0[2], a0[3],
                  sb + PSW + ((lane & 15)) * PW_STR + ch * 64 + kt * 32 + (lane >> 4) * 16);
            ldsm4(a1[0], a1[1], a1[2], a1[3],
                  sb + PSW + (16 + (lane & 15)) * PW_STR + ch * 64 + kt * 32 + (lane >> 4) * 16);
            uint32_t xrow = kt * 16 + ((lane >> 3) & 1) * 8 + (lane & 7);
#pragma unroll
            for (int nb = 0; nb < 2; ++nb) {
                uint32_t colb = nw * 2 + nb * 32 + ((lane >> 4) & 1) * 16;
                uint32_t b0, b1, b2, b3;
                ldsm4t(b0, b1, b2, b3, sb + PSX(st) + xrow * PX_STR + colb);
                int j = nb * 2;
                mma_f16(O[0][j],     a0[0], a0[1], a0[2], a0[3], b0, b1);
                mma_f16(O[0][j + 1], a0[0], a0[1], a0[2], a0[3], b2, b3);
                mma_f16(O[1][j],     a1[0], a1[1], a1[2], a1[3], b0, b1);
                mma_f16(O[1][j + 1], a1[0], a1[1], a1[2], a1[3], b2, b3);
            }
        }

        if (ch < 7) cvt_store(f, st ^ 1);
        __syncthreads();
    }

    {
        int g = lane >> 3;
#pragma unroll
        for (int mt = 0; mt < 2; ++mt) {
            float bias0 = g_Bf[r0 + mt * 16 + (lane >> 2)] * qs;
            float bias1 = g_Bf[r0 + mt * 16 + (lane >> 2) + 8] * qs;
            uint32_t p01[4], p23[4];
#pragma unroll
            for (int j = 0; j < 4; ++j) {
                __half2 h01 = __floats2half2_rn(O[mt][j][0] + bias0, O[mt][j][1] + bias0);
                __half2 h23 = __floats2half2_rn(O[mt][j][2] + bias1, O[mt][j][3] + bias1);
                p01[j] = *reinterpret_cast<uint32_t*>(&h01);
                p23[j] = *reinterpret_cast<uint32_t*>(&h23);
            }
            uint32_t row = mt * 16 + (g & 1) * 8 + (lane & 7);
            uint32_t colb = nw * 2 + (g >> 1) * 16;
            uint32_t a0 = sb + PSX(0) + row * PX_STR + colb;
            stsm4(a0,      p01[0], p23[0], p01[1], p23[1]);
            stsm4(a0 + 32, p01[2], p23[2], p01[3], p23[3]);
        }
    }
    __syncthreads();

    {
        uint32_t h[16];
#pragma unroll
        for (int j = 0; j < 16; ++j) {
            uint16_t lo, hi;
            asm volatile("ld.shared.u16 %0, [%1];" : "=h"(lo)
                         : "r"(sb + PSX(0) + (2 * j) * PX_STR + tid * 2));
            asm volatile("ld.shared.u16 %0, [%1];" : "=h"(hi)
                         : "r"(sb + PSX(0) + (2 * j + 1) * PX_STR + tid * 2));
            h[j] = (uint32_t)lo | ((uint32_t)hi << 16);
        }
        char* dst;
        if (seg < 2)
            dst = (char*)((seg == 0) ? g_Qs : g_Ks) + ((size_t)(b * N_PIX + px0 + tid)) * 64;
        else
            dst = (char*)g_V + (((size_t)(b * N_PIX + px0 + tid)) * C_IN + (seg - 2) * 32) * 2;
#pragma unroll
        for (int q = 0; q < 4; ++q)
            *(uint4*)(dst + q * 16) = make_uint4(h[4 * q], h[4 * q + 1], h[4 * q + 2], h[4 * q + 3]);
    }
}

// ---------------- flash attention: R13/R14 structure + Q hoist + coalesced epilogue ----------------
// grid: (N_PIX/64, B), 256 threads = 8 warps, occ 2.
__global__ __launch_bounds__(256, 2) void flash_mma(float* __restrict__ out)
{
    extern __shared__ __align__(16) char sm[];
    const uint32_t sb = s2u(sm);
    const int tid  = threadIdx.x;
    const int warp = tid >> 5;
    const int lane = tid & 31;
    const int ms   = (warp & 3) * 16;    // S-phase m slice
    const int half = warp >> 2;          // S-phase n half
    const int mw   = (warp & 1) * 32;    // PV m base
    const int cq   = (warp >> 1) * 64;   // PV c quarter
    const int b    = blockIdx.y;
    const int m_base = blockIdx.x * M_TILE;

    const char* gkb = (const char*)g_Ks + ((size_t)b * N_PIX) * 64;
    const char* gvb = (const char*)g_V + ((size_t)b * N_PIX) * C_IN * 2;

    // ---- Q tile -> smem ----
    {
        const char* gq = (const char*)g_Qs + ((size_t)(b * N_PIX + m_base)) * 64;
        int m = tid >> 2, q = tid & 3;
        uint4 v = *(const uint4*)(gq + (size_t)m * 64 + q * 16);
        *(uint4*)(sm + SQ + m * QK_STR + q * 16) = v;
    }

    float O[2][8][4];
#pragma unroll
    for (int mt = 0; mt < 2; ++mt)
#pragma unroll
        for (int j = 0; j < 8; ++j)
#pragma unroll
            for (int k = 0; k < 4; ++k) O[mt][j][k] = 0.f;
    float rs0 = 0.f, rs1 = 0.f;

    auto load_k = [&](int t, int st) {
        const char* gk = gkb + (size_t)t * TN * 64;
        for (int i = tid; i < 512; i += 256) {
            int n = i >> 2, q = i & 3;
            cp16(sb + SKB(st) + n * QK_STR + q * 16, gk + (size_t)n * 64 + q * 16);
        }
    };
    auto load_v = [&](int t) {
        const char* gv = gvb + (size_t)t * TN * C_IN * 2;
        for (int i = tid; i < 4096; i += 256) {
            int n = i >> 5, q = i & 31;
            cp16(sb + SV + n * V_STR + q * 16, gv + (size_t)n * 512 + q * 16);
        }
    };

    load_k(0, 0);
    CP_COMMIT();
    load_v(0);
    CP_COMMIT();
    __syncthreads();   // Q smem visible

    // ---- hoist Q fragments (loop-invariant across all tiles and np) ----
    uint32_t qf[2][4];
#pragma unroll
    for (int kt = 0; kt < 2; ++kt)
        ldsm4(qf[kt][0], qf[kt][1], qf[kt][2], qf[kt][3],
              sb + SQ + (ms + (lane & 15)) * QK_STR + kt * 32 + (lane >> 4) * 16);

#pragma unroll 1
    for (int t = 0; t < NTILES; ++t) {
        const int st = t & 1;
        if (t + 1 < NTILES) {
            load_k(t + 1, st ^ 1);
            CP_COMMIT();
            CP_WAITN(2);   // K(t) done; V(t), K(t+1) in flight
        } else {
            CP_WAITN(1);   // K(t) done; V(t) in flight
        }
        __syncthreads();

        // ---- S = Q K^T, two n32 sub-passes ----
#pragma unroll
        for (int np = 0; np < 2; ++np) {
            float acc[4][4];
#pragma unroll
            for (int j = 0; j < 4; ++j)
#pragma unroll
                for (int k = 0; k < 4; ++k) acc[j][k] = 0.f;

#pragma unroll
            for (int kt = 0; kt < 2; ++kt) {
#pragma unroll
                for (int nb = 0; nb < 2; ++nb) {
                    int nbase = half * 64 + np * 32 + nb * 16;
                    uint32_t row = nbase + ((lane >> 4) << 3) + (lane & 7);
                    uint32_t col = kt * 32 + ((lane >> 3) & 1) * 16;
                    uint32_t b0, b1, b2, b3;
                    ldsm4(b0, b1, b2, b3, sb + SKB(st) + row * QK_STR + col);
                    mma_f16(acc[2 * nb],     qf[kt][0], qf[kt][1], qf[kt][2], qf[kt][3], b0, b1);
                    mma_f16(acc[2 * nb + 1], qf[kt][0], qf[kt][1], qf[kt][2], qf[kt][3], b2, b3);
                }
            }

            // P = exp2(S) unnormalized; row sums; pack fp16
            uint32_t p01h[4], p23h[4];
#pragma unroll
            for (int j = 0; j < 4; ++j) {
                float p0 = ex2f(acc[j][0]), p1 = ex2f(acc[j][1]);
                float p2 = ex2f(acc[j][2]), p3 = ex2f(acc[j][3]);
                rs0 += p0 + p1;
                rs1 += p2 + p3;
                __half2 h01 = __floats2half2_rn(p0, p1);
                __half2 h23 = __floats2half2_rn(p2, p3);
                p01h[j] = *reinterpret_cast<uint32_t*>(&h01);
                p23h[j] = *reinterpret_cast<uint32_t*>(&h23);
            }

            // stsm P: [64 m][128 k]
            int g = lane >> 3;
            uint32_t row = ms + (g & 1) * 8 + (lane & 7);
            uint32_t colb = half * 128 + np * 64 + (g >> 1) * 16;
            uint32_t a0 = sb + SP + row * P_STR + colb;
            stsm4(a0,      p01h[0], p23h[0], p01h[1], p23h[1]);
            stsm4(a0 + 32, p01h[2], p23h[2], p01h[3], p23h[3]);
        }

        // ---- wait V(t), then PV: warp m32 x c64 ----
        if (t + 1 < NTILES) CP_WAITN(1);
        else                CP_WAITN(0);
        __syncthreads();

#pragma unroll
        for (int kt = 0; kt < 8; ++kt) {
            uint32_t p0a, p0b, p0c, p0d, p1a, p1b, p1c, p1d;
            ldsm4(p0a, p0b, p0c, p0d,
                  sb + SP + (mw + (lane & 15)) * P_STR + kt * 32 + (lane >> 4) * 16);
            ldsm4(p1a, p1b, p1c, p1d,
                  sb + SP + (mw + 16 + (lane & 15)) * P_STR + kt * 32 + (lane >> 4) * 16);
            uint32_t vrow = kt * 16 + ((lane >> 3) & 1) * 8 + (lane & 7);
#pragma unroll
            for (int vb = 0; vb < 4; ++vb) {
                uint32_t colb = cq * 2 + vb * 32 + ((lane >> 4) & 1) * 16;
                uint32_t b0, b1, b2, b3;
                ldsm4t(b0, b1, b2, b3, sb + SV + vrow * V_STR + colb);
                int j = vb * 2;
                mma_f16(O[0][j],     p0a, p0b, p0c, p0d, b0, b1);
                mma_f16(O[0][j + 1], p0a, p0b, p0c, p0d, b2, b3);
                mma_f16(O[1][j],     p1a, p1b, p1c, p1d, b0, b1);
                mma_f16(O[1][j + 1], p1a, p1b, p1c, p1d, b2, b3);
            }
        }
        __syncthreads();

        if (t + 1 < NTILES) {
            load_v(t + 1);
            CP_COMMIT();
        }
    }

    // ---- epilogue: row sums -> inv, stage O in smem [256 c][64 m], coalesced STG ----
    rs0 += __shfl_xor_sync(0xffffffffu, rs0, 1);
    rs0 += __shfl_xor_sync(0xffffffffu, rs0, 2);
    rs1 += __shfl_xor_sync(0xffffffffu, rs1, 1);
    rs1 += __shfl_xor_sync(0xffffffffu, rs1, 2);
    float* sLp = (float*)(sm + SLP);
    if ((lane & 3) == 0) {
        sLp[half * 64 + ms + (lane >> 2)]     = rs0;
        sLp[half * 64 + ms + (lane >> 2) + 8] = rs1;
    }
    __syncthreads();   // also orders: all PV smem reads done before sT overwrites tiles

    float* sT = (float*)sm;   // [256 c][T_STR] floats = 69632 B (tile regions dead)
#pragma unroll
    for (int mt = 0; mt < 2; ++mt) {
        int r0 = mw + mt * 16 + (lane >> 2);
        float inv0 = 1.0f / (sLp[r0] + sLp[64 + r0]);
        float inv1 = 1.0f / (sLp[r0 + 8] + sLp[64 + r0 + 8]);
#pragma unroll
        for (int j = 0; j < 8; ++j) {
            int c = cq + j * 8 + 2 * (lane & 3);
            sT[c * T_STR + r0]           = O[mt][j][0] * inv0;
            sT[(c + 1) * T_STR + r0]     = O[mt][j][1] * inv0;
            sT[c * T_STR + r0 + 8]       = O[mt][j][2] * inv1;
            sT[(c + 1) * T_STR + r0 + 8] = O[mt][j][3] * inv1;
        }
    }
    __syncthreads();

    // stream out: 256 c-rows x 64 m floats, 16B chunks, half-warp contiguous
    {
        float* ob = out + (size_t)b * C_IN * N_PIX + m_base;
#pragma unroll
        for (int k = 0; k < 16; ++k) {
            int idx = tid + k * 256;
            int c = idx >> 4, mq = idx & 15;
            float4 v = *(const float4*)&sT[c * T_STR + mq * 4];
            *(float4*)&ob[(size_t)c * N_PIX + mq * 4] = v;
        }
    }
}

// ---------------- launch ----------------
extern "C" void kernel_launch(void* const* d_in, const int* in_sizes, int n_in,
                              void* d_out, int out_size)
{
    const float* x1 = (const float*)d_in[0];
    const float* x2 = (const float*)d_in[1];

    fold_kernel<<<320, 256>>>(
        (const float*)d_in[2],  (const float*)d_in[3],  (const float*)d_in[4],
        (const float*)d_in[5],  (const float*)d_in[6],  (const float*)d_in[7],
        (const float*)d_in[8],  (const float*)d_in[9],  (const float*)d_in[10],
        (const float*)d_in[11], (const float*)d_in[12], (const float*)d_in[13],
        (const float*)d_in[14], (const float*)d_in[15], (const float*)d_in[16],
        (const float*)d_in[17], (const float*)d_in[18], (const float*)d_in[19]);

    proj2_kernel<<<dim3(N_PIX / 256, 10, B_SZ), 256>>>(x1, x2);

    cudaFuncSetAttribute(flash_mma, cudaFuncAttributeMaxDynamicSharedMemorySize, SMEM_TOTAL);
    flash_mma<<<dim3(N_PIX / M_TILE, B_SZ), 256, SMEM_TOTAL>>>((float*)d_out);
}